// round 1
// baseline (speedup 1.0000x reference)
#include <cuda_runtime.h>
#include <cuda_bf16.h>
#include <math.h>

// ---------------- problem constants ----------------
#define B_  4
#define T_  2048
#define C_  1024
#define H_  8
#define DH_ 128
#define DFF_ 4096
#define M_  (B_ * T_)            // 8192 rows

// ---------------- scratch (device globals, no allocation) ----------------
__device__ float g_h1[M_ * C_];                       // LN1 output
__device__ float g_q [B_ * H_ * T_ * DH_];
__device__ float g_k [B_ * H_ * T_ * DH_];
__device__ float g_v [B_ * H_ * T_ * DH_];
__device__ float g_sc[(size_t)B_ * H_ * T_ * T_];     // 512 MB scores / probs
__device__ float g_x1[M_ * C_];                       // x + attn_out
__device__ float g_h2[M_ * C_];                       // LN2 output
__device__ float g_f1[M_ * DFF_];                     // relu(h2 w1 + b1)

// ---------------- shared GEMM core: 128x128 tile, 8x8/thread, Ktile=8 ----------------
#define BSTR 132   // padded smem row stride (conflict-free scatter stores)

template<bool TB>
__device__ __forceinline__ void gemm_core(const float* __restrict__ A, int lda,
                                          const float* __restrict__ B, int ldb,
                                          int K, float acc[8][8])
{
    __shared__ float As[8 * BSTR];
    __shared__ float Bs[8 * BSTR];
    const int tid = threadIdx.x;
    const int tx  = tid & 15;
    const int ty  = tid >> 4;
    const int lm  = tid >> 1;          // 0..127  (row of A tile / row of B^T tile)
    const int lk4 = (tid & 1) * 4;     // 0 or 4
    const int bk  = tid >> 5;          // 0..7    (NN B loader)
    const int bn4 = (tid & 31) * 4;

    for (int kt = 0; kt < K; kt += 8) {
        // ---- load A tile (rows lm, cols kt..kt+7), transpose into As[k][m]
        float4 av = *(const float4*)(A + (size_t)lm * lda + kt + lk4);
        As[(lk4 + 0) * BSTR + lm] = av.x;
        As[(lk4 + 1) * BSTR + lm] = av.y;
        As[(lk4 + 2) * BSTR + lm] = av.z;
        As[(lk4 + 3) * BSTR + lm] = av.w;
        if (TB) {
            // B is [N,K] row-major; Bs[k][n] = B[n][k]
            float4 bv = *(const float4*)(B + (size_t)lm * ldb + kt + lk4);
            Bs[(lk4 + 0) * BSTR + lm] = bv.x;
            Bs[(lk4 + 1) * BSTR + lm] = bv.y;
            Bs[(lk4 + 2) * BSTR + lm] = bv.z;
            Bs[(lk4 + 3) * BSTR + lm] = bv.w;
        } else {
            // B is [K,N] row-major
            float4 bv = *(const float4*)(B + (size_t)(kt + bk) * ldb + bn4);
            *(float4*)(&Bs[bk * BSTR + bn4]) = bv;
        }
        __syncthreads();

        #pragma unroll
        for (int kk = 0; kk < 8; kk++) {
            float a[8], b[8];
            *(float4*)(a)     = *(const float4*)(&As[kk * BSTR + ty * 8]);
            *(float4*)(a + 4) = *(const float4*)(&As[kk * BSTR + ty * 8 + 4]);
            *(float4*)(b)     = *(const float4*)(&Bs[kk * BSTR + tx * 8]);
            *(float4*)(b + 4) = *(const float4*)(&Bs[kk * BSTR + tx * 8 + 4]);
            #pragma unroll
            for (int i = 0; i < 8; i++)
                #pragma unroll
                for (int j = 0; j < 8; j++)
                    acc[i][j] += a[i] * b[j];
        }
        __syncthreads();
    }
}

// ---------------- LayerNorm ----------------
__device__ __forceinline__ void block_reduce2(float& a, float& b)
{
    #pragma unroll
    for (int o = 16; o; o >>= 1) {
        a += __shfl_xor_sync(0xFFFFFFFFu, a, o);
        b += __shfl_xor_sync(0xFFFFFFFFu, b, o);
    }
    __shared__ float sa[8], sb[8];
    int w = threadIdx.x >> 5, l = threadIdx.x & 31;
    if (l == 0) { sa[w] = a; sb[w] = b; }
    __syncthreads();
    a = 0.f; b = 0.f;
    #pragma unroll
    for (int i = 0; i < 8; i++) { a += sa[i]; b += sb[i]; }
}

__global__ void ln_kernel(const float* __restrict__ x, const float* __restrict__ g,
                          const float* __restrict__ bb, float* __restrict__ out)
{
    size_t row = blockIdx.x;
    const float4* xr = (const float4*)(x + row * C_);
    float4 v = xr[threadIdx.x];
    float s  = v.x + v.y + v.z + v.w;
    float sq = v.x * v.x + v.y * v.y + v.z * v.z + v.w * v.w;
    block_reduce2(s, sq);
    float mean = s * (1.0f / C_);
    float var  = sq * (1.0f / C_) - mean * mean;
    float inv  = rsqrtf(var + 1e-5f);
    float4 gv = ((const float4*)g)[threadIdx.x];
    float4 bv = ((const float4*)bb)[threadIdx.x];
    float4 o;
    o.x = (v.x - mean) * inv * gv.x + bv.x;
    o.y = (v.y - mean) * inv * gv.y + bv.y;
    o.z = (v.z - mean) * inv * gv.z + bv.z;
    o.w = (v.w - mean) * inv * gv.w + bv.w;
    ((float4*)(out + row * C_))[threadIdx.x] = o;
}

// ---------------- QKV projection ----------------
__global__ __launch_bounds__(256, 2)
void qkv_kernel(const float* __restrict__ wq, const float* __restrict__ wk,
                const float* __restrict__ wv)
{
    int m0   = blockIdx.x * 128;
    int sel  = blockIdx.y >> 3;
    int head = blockIdx.y & 7;
    const float* W = (sel == 0 ? wq : sel == 1 ? wk : wv) + (size_t)head * C_ * DH_;
    float* O = (sel == 0 ? g_q : sel == 1 ? g_k : g_v);

    float acc[8][8] = {};
    gemm_core<false>(g_h1 + (size_t)m0 * C_, C_, W, DH_, C_, acc);

    int tx = threadIdx.x & 15, ty = threadIdx.x >> 4;
    #pragma unroll
    for (int i = 0; i < 8; i++) {
        int m = m0 + ty * 8 + i;
        int b = m >> 11, t = m & (T_ - 1);
        float* dst = O + ((size_t)(b * H_ + head) * T_ + t) * DH_ + tx * 8;
        *(float4*)(dst)     = make_float4(acc[i][0], acc[i][1], acc[i][2], acc[i][3]);
        *(float4*)(dst + 4) = make_float4(acc[i][4], acc[i][5], acc[i][6], acc[i][7]);
    }
}

// ---------------- scores = q k^T * sqrt(Dh) ----------------
__global__ __launch_bounds__(256, 2)
void scores_kernel()
{
    int z  = blockIdx.z;                         // b*H + h
    int m0 = blockIdx.x * 128, n0 = blockIdx.y * 128;
    const float* A = g_q + (size_t)z * T_ * DH_ + (size_t)m0 * DH_;
    const float* Bm = g_k + (size_t)z * T_ * DH_ + (size_t)n0 * DH_;

    float acc[8][8] = {};
    gemm_core<true>(A, DH_, Bm, DH_, DH_, acc);

    const float alpha = 11.313708498984761f;     // sqrt(128)
    int tx = threadIdx.x & 15, ty = threadIdx.x >> 4;
    float* out = g_sc + (size_t)z * T_ * T_ + (size_t)m0 * T_ + n0;
    #pragma unroll
    for (int i = 0; i < 8; i++) {
        float* dst = out + (size_t)(ty * 8 + i) * T_ + tx * 8;
        *(float4*)(dst)     = make_float4(acc[i][0]*alpha, acc[i][1]*alpha, acc[i][2]*alpha, acc[i][3]*alpha);
        *(float4*)(dst + 4) = make_float4(acc[i][4]*alpha, acc[i][5]*alpha, acc[i][6]*alpha, acc[i][7]*alpha);
    }
}

// ---------------- row softmax over 2048 ----------------
__global__ void softmax_kernel()
{
    size_t row = blockIdx.x;
    float* p = g_sc + row * T_;
    float4 v0 = *(float4*)(p + threadIdx.x * 8);
    float4 v1 = *(float4*)(p + threadIdx.x * 8 + 4);

    float mx = fmaxf(fmaxf(fmaxf(v0.x, v0.y), fmaxf(v0.z, v0.w)),
                     fmaxf(fmaxf(v1.x, v1.y), fmaxf(v1.z, v1.w)));
    #pragma unroll
    for (int o = 16; o; o >>= 1) mx = fmaxf(mx, __shfl_xor_sync(0xFFFFFFFFu, mx, o));
    __shared__ float sm[8];
    int w = threadIdx.x >> 5, l = threadIdx.x & 31;
    if (l == 0) sm[w] = mx;
    __syncthreads();
    mx = fmaxf(fmaxf(fmaxf(sm[0], sm[1]), fmaxf(sm[2], sm[3])),
               fmaxf(fmaxf(sm[4], sm[5]), fmaxf(sm[6], sm[7])));

    v0.x = expf(v0.x - mx); v0.y = expf(v0.y - mx); v0.z = expf(v0.z - mx); v0.w = expf(v0.w - mx);
    v1.x = expf(v1.x - mx); v1.y = expf(v1.y - mx); v1.z = expf(v1.z - mx); v1.w = expf(v1.w - mx);
    float s = v0.x + v0.y + v0.z + v0.w + v1.x + v1.y + v1.z + v1.w;
    float s2 = s;
    __syncthreads();   // reuse sm[]
    block_reduce2(s, s2);
    float inv = 1.0f / s;
    v0.x *= inv; v0.y *= inv; v0.z *= inv; v0.w *= inv;
    v1.x *= inv; v1.y *= inv; v1.z *= inv; v1.w *= inv;
    *(float4*)(p + threadIdx.x * 8)     = v0;
    *(float4*)(p + threadIdx.x * 8 + 4) = v1;
}

// ---------------- o = P @ V ; x1 = x + concat(o) ----------------
__global__ __launch_bounds__(256, 2)
void o_kernel(const float* __restrict__ x)
{
    int z = blockIdx.z;
    int b = z >> 3, head = z & 7;
    int m0 = blockIdx.x * 128;
    const float* A  = g_sc + (size_t)z * T_ * T_ + (size_t)m0 * T_;
    const float* Bm = g_v  + (size_t)z * T_ * DH_;

    float acc[8][8] = {};
    gemm_core<false>(A, T_, Bm, DH_, T_, acc);

    int tx = threadIdx.x & 15, ty = threadIdx.x >> 4;
    #pragma unroll
    for (int i = 0; i < 8; i++) {
        int t = m0 + ty * 8 + i;
        size_t idx = ((size_t)(b * T_ + t)) * C_ + head * DH_ + tx * 8;
        float4 r0 = *(const float4*)(x + idx);
        float4 r1 = *(const float4*)(x + idx + 4);
        *(float4*)(g_x1 + idx)     = make_float4(acc[i][0]+r0.x, acc[i][1]+r0.y, acc[i][2]+r0.z, acc[i][3]+r0.w);
        *(float4*)(g_x1 + idx + 4) = make_float4(acc[i][4]+r1.x, acc[i][5]+r1.y, acc[i][6]+r1.z, acc[i][7]+r1.w);
    }
}

// ---------------- ff1 = relu(h2 @ w1 + b1) ----------------
__global__ __launch_bounds__(256, 2)
void ff1_kernel(const float* __restrict__ w1, const float* __restrict__ b1)
{
    int m0 = blockIdx.x * 128, n0 = blockIdx.y * 128;
    float acc[8][8] = {};
    gemm_core<false>(g_h2 + (size_t)m0 * C_, C_, w1 + n0, DFF_, C_, acc);

    int tx = threadIdx.x & 15, ty = threadIdx.x >> 4;
    float4 bv0 = *(const float4*)(b1 + n0 + tx * 8);
    float4 bv1 = *(const float4*)(b1 + n0 + tx * 8 + 4);
    #pragma unroll
    for (int i = 0; i < 8; i++) {
        float* dst = g_f1 + (size_t)(m0 + ty * 8 + i) * DFF_ + n0 + tx * 8;
        *(float4*)(dst) = make_float4(fmaxf(acc[i][0]+bv0.x, 0.f), fmaxf(acc[i][1]+bv0.y, 0.f),
                                      fmaxf(acc[i][2]+bv0.z, 0.f), fmaxf(acc[i][3]+bv0.w, 0.f));
        *(float4*)(dst + 4) = make_float4(fmaxf(acc[i][4]+bv1.x, 0.f), fmaxf(acc[i][5]+bv1.y, 0.f),
                                          fmaxf(acc[i][6]+bv1.z, 0.f), fmaxf(acc[i][7]+bv1.w, 0.f));
    }
}

// ---------------- out = x1 + ff1 @ w2 + b2 ----------------
__global__ __launch_bounds__(256, 2)
void ff2_kernel(const float* __restrict__ w2, const float* __restrict__ b2,
                float* __restrict__ out)
{
    int m0 = blockIdx.x * 128, n0 = blockIdx.y * 128;
    float acc[8][8] = {};
    gemm_core<false>(g_f1 + (size_t)m0 * DFF_, DFF_, w2 + n0, C_, DFF_, acc);

    int tx = threadIdx.x & 15, ty = threadIdx.x >> 4;
    float4 bv0 = *(const float4*)(b2 + n0 + tx * 8);
    float4 bv1 = *(const float4*)(b2 + n0 + tx * 8 + 4);
    #pragma unroll
    for (int i = 0; i < 8; i++) {
        size_t idx = (size_t)(m0 + ty * 8 + i) * C_ + n0 + tx * 8;
        float4 r0 = *(const float4*)(g_x1 + idx);
        float4 r1 = *(const float4*)(g_x1 + idx + 4);
        *(float4*)(out + idx)     = make_float4(acc[i][0]+bv0.x+r0.x, acc[i][1]+bv0.y+r0.y,
                                                acc[i][2]+bv0.z+r0.z, acc[i][3]+bv0.w+r0.w);
        *(float4*)(out + idx + 4) = make_float4(acc[i][4]+bv1.x+r1.x, acc[i][5]+bv1.y+r1.y,
                                                acc[i][6]+bv1.z+r1.z, acc[i][7]+bv1.w+r1.w);
    }
}

// ---------------- host ----------------
extern "C" void kernel_launch(void* const* d_in, const int* in_sizes, int n_in,
                              void* d_out, int out_size)
{
    const float* x     = (const float*)d_in[0];
    const float* wq    = (const float*)d_in[1];
    const float* wk    = (const float*)d_in[2];
    const float* wv    = (const float*)d_in[3];
    const float* w1    = (const float*)d_in[4];
    const float* b1    = (const float*)d_in[5];
    const float* w2    = (const float*)d_in[6];
    const float* b2    = (const float*)d_in[7];
    const float* ln1_g = (const float*)d_in[8];
    const float* ln1_b = (const float*)d_in[9];
    const float* ln2_g = (const float*)d_in[10];
    const float* ln2_b = (const float*)d_in[11];
    float* out = (float*)d_out;

    float *p_h1, *p_x1, *p_h2;
    cudaGetSymbolAddress((void**)&p_h1, g_h1);
    cudaGetSymbolAddress((void**)&p_x1, g_x1);
    cudaGetSymbolAddress((void**)&p_h2, g_h2);

    // 1. LN1
    ln_kernel<<<M_, 256>>>(x, ln1_g, ln1_b, p_h1);
    // 2. QKV
    qkv_kernel<<<dim3(M_ / 128, 3 * H_, 1), 256>>>(wq, wk, wv);
    // 3. scores
    scores_kernel<<<dim3(T_ / 128, T_ / 128, B_ * H_), 256>>>();
    // 4. softmax
    softmax_kernel<<<B_ * H_ * T_, 256>>>();
    // 5. attention out + residual
    o_kernel<<<dim3(T_ / 128, 1, B_ * H_), 256>>>(x);
    // 6. LN2
    ln_kernel<<<M_, 256>>>(p_x1, ln2_g, ln2_b, p_h2);
    // 7. FF1
    ff1_kernel<<<dim3(M_ / 128, DFF_ / 128, 1), 256>>>(w1, b1);
    // 8. FF2 (+bias +residual) -> out
    ff2_kernel<<<dim3(M_ / 128, C_ / 128, 1), 256>>>(w2, b2, out);
}